// round 15
// baseline (speedup 1.0000x reference)
#include <cuda_runtime.h>
#include <cuda_bf16.h>
#include <cstdint>

#define N_NODES 100000
#define N_EDGES 320000
#define DIM 256
#define PAD_ROWS 128

#define SCAN_B 256
#define NBLK ((N_NODES + SCAN_B - 1) / SCAN_B)

// ---------------- scratch (no allocations allowed) ----------------
__device__ int   g_deg_out[N_NODES];
__device__ int   g_deg_in[N_NODES];
__device__ float g_inv_out[N_NODES];
__device__ float g_inv_in[N_NODES];
__device__ float g_h[(size_t)N_NODES * DIM];
// gather output, pre-split bf16 (padded so full GEMM tiles read in-bounds)
__device__ __nv_bfloat16 g_a_hi[(size_t)(N_NODES + PAD_ROWS) * DIM];
__device__ __nv_bfloat16 g_a_lo[(size_t)(N_NODES + PAD_ROWS) * DIM];
// CSR (by dst): source index + pre-looked-up edge weight
__device__ int   g_off[N_NODES + 1];
__device__ int   g_cur[N_NODES];
__device__ int   g_part[NBLK];
__device__ int   g_esrc[N_EDGES];
__device__ float g_ew[N_EDGES];
// W transposed to [N,K], bf16 hi/lo
__device__ __nv_bfloat16 g_bt1_hi[DIM * DIM];
__device__ __nv_bfloat16 g_bt1_lo[DIM * DIM];
__device__ __nv_bfloat16 g_bt2_hi[DIM * DIM];
__device__ __nv_bfloat16 g_bt2_lo[DIM * DIM];

// ---------------- helpers ----------------
__device__ __forceinline__ uint32_t smem_u32(const void* p) {
    uint32_t a;
    asm("{ .reg .u64 t; cvta.to.shared.u64 t, %1; cvt.u32.u64 %0, t; }" : "=r"(a) : "l"(p));
    return a;
}
__device__ __forceinline__ void cp16(uint32_t dst, const void* src) {
    asm volatile("cp.async.cg.shared.global [%0], [%1], 16;"
                 :: "r"(dst), "l"(src) : "memory");
}
__device__ __forceinline__ void cp_commit() {
    asm volatile("cp.async.commit_group;" ::: "memory");
}
__device__ __forceinline__ void cp_wait0() {
    asm volatile("cp.async.wait_group 0;" ::: "memory");
}
__device__ __forceinline__ void ldm4(uint32_t* r, uint32_t addr) {
    asm volatile("ldmatrix.sync.aligned.m8n8.x4.shared.b16 {%0,%1,%2,%3}, [%4];"
                 : "=r"(r[0]), "=r"(r[1]), "=r"(r[2]), "=r"(r[3]) : "r"(addr));
}
__device__ __forceinline__ void mma16816(float* c, const uint32_t* a, uint32_t b0, uint32_t b1) {
    asm volatile("mma.sync.aligned.m16n8k16.row.col.f32.bf16.bf16.f32 "
                 "{%0,%1,%2,%3}, {%4,%5,%6,%7}, {%8,%9}, {%0,%1,%2,%3};"
                 : "+f"(c[0]), "+f"(c[1]), "+f"(c[2]), "+f"(c[3])
                 : "r"(a[0]), "r"(a[1]), "r"(a[2]), "r"(a[3]), "r"(b0), "r"(b1));
}
__device__ __forceinline__ uint32_t pack_hi(float x, float y) {
    return (uint32_t)__bfloat16_as_ushort(__float2bfloat16(x)) |
           ((uint32_t)__bfloat16_as_ushort(__float2bfloat16(y)) << 16);
}
__device__ __forceinline__ uint32_t pack_lo(float x, float y) {
    float rx = x - __bfloat162float(__float2bfloat16(x));
    float ry = y - __bfloat162float(__float2bfloat16(y));
    return (uint32_t)__bfloat16_as_ushort(__float2bfloat16(rx)) |
           ((uint32_t)__bfloat16_as_ushort(__float2bfloat16(ry)) << 16);
}
__device__ __forceinline__ void st_cs_u2(void* p, uint2 v) {
    asm volatile("st.global.cs.v2.u32 [%0], {%1, %2};"
                 :: "l"(p), "r"(v.x), "r"(v.y) : "memory");
}
__device__ __forceinline__ void fma4(float4& a, float w, const float4& v) {
    a.x = fmaf(w, v.x, a.x); a.y = fmaf(w, v.y, a.y);
    a.z = fmaf(w, v.z, a.z); a.w = fmaf(w, v.w, a.w);
}

// ---------------- graph prep (compact: 5 launches) ----------------
__global__ void k_init_counts() {
    int i = blockIdx.x * blockDim.x + threadIdx.x;
    if (i < N_NODES) { g_deg_out[i] = 0; g_deg_in[i] = 0; }
}
// degree count + weight split fused (independent work, one launch)
__global__ void k_count_prep(const int* __restrict__ src, const int* __restrict__ dst,
                             const float* __restrict__ W1, const float* __restrict__ W2) {
    int i = blockIdx.x * blockDim.x + threadIdx.x;
    if (i < N_EDGES) {
        atomicAdd(&g_deg_out[src[i]], 1);
        atomicAdd(&g_deg_in[dst[i]], 1);
    }
    if (i < 2 * DIM * DIM) {
        int layer = i >= DIM * DIM;
        int j = i - layer * DIM * DIM;
        int n = j >> 8, k = j & 255;
        float v = layer ? W2[k * DIM + n] : W1[k * DIM + n];
        __nv_bfloat16 h = __float2bfloat16(v);
        float l = v - __bfloat162float(h);
        if (layer) { g_bt2_hi[j] = h; g_bt2_lo[j] = __float2bfloat16(l); }
        else       { g_bt1_hi[j] = h; g_bt1_lo[j] = __float2bfloat16(l); }
    }
}
__global__ void k_scan1() {
    __shared__ int sh[SCAN_B];
    int i = blockIdx.x * SCAN_B + threadIdx.x;
    int v = (i < N_NODES) ? g_deg_in[i] : 0;
    sh[threadIdx.x] = v;
    __syncthreads();
#pragma unroll
    for (int o = 1; o < SCAN_B; o <<= 1) {
        int t = (threadIdx.x >= o) ? sh[threadIdx.x - o] : 0;
        __syncthreads();
        sh[threadIdx.x] += t;
        __syncthreads();
    }
    if (i < N_NODES) g_off[i] = sh[threadIdx.x] - v;
    if (threadIdx.x == SCAN_B - 1) g_part[blockIdx.x] = sh[SCAN_B - 1];
}
// per-block prefix of partials computed redundantly (replaces scan2)
__global__ void k_scan3_inv() {
    __shared__ int sred[SCAN_B];
    int t = threadIdx.x, b = blockIdx.x;
    int acc = 0;
    for (int j = t; j < b; j += SCAN_B) acc += g_part[j];
    sred[t] = acc;
    __syncthreads();
#pragma unroll
    for (int o = SCAN_B / 2; o > 0; o >>= 1) {
        if (t < o) sred[t] += sred[t + o];
        __syncthreads();
    }
    int prefix = sred[0];
    int i = b * SCAN_B + t;
    if (i < N_NODES) {
        int o = g_off[i] + prefix;
        g_off[i] = o;
        g_cur[i] = o;
        g_inv_out[i] = rsqrtf(fmaxf((float)g_deg_out[i], 1.0f));
        g_inv_in[i]  = rsqrtf(fmaxf((float)g_deg_in[i], 1.0f));
    }
    if (i == 0) g_off[N_NODES] = N_EDGES;
}
// bucket edges by dst; also pre-look-up the src-side weight per edge
__global__ void k_bucket(const int* __restrict__ src, const int* __restrict__ dst) {
    int e = blockIdx.x * blockDim.x + threadIdx.x;
    if (e < N_EDGES) {
        int s = src[e];
        int p = atomicAdd(&g_cur[dst[e]], 1);
        g_esrc[p] = s;
        g_ew[p]   = g_inv_out[s];
    }
}

// ---------------- CSR gather + bf16 split (champion R13 form, ew stream) ----------------
// One warp per node; lane owns float4 cols {4*lane, 4*lane+128}. 4-edge MLP batches.
__global__ __launch_bounds__(256)
void k_gather(const float* __restrict__ feat) {
    int node = (blockIdx.x * blockDim.x + threadIdx.x) >> 5;
    int lane = threadIdx.x & 31;
    if (node >= N_NODES) return;
    int e0 = g_off[node], e1 = g_off[node + 1];

    float4 a0 = make_float4(0.f, 0.f, 0.f, 0.f);
    float4 a1 = a0;

    int e = e0;
    for (; e + 4 <= e1; e += 4) {
        int   s0 = g_esrc[e],     s1 = g_esrc[e + 1];
        int   s2 = g_esrc[e + 2], s3 = g_esrc[e + 3];
        float w0 = g_ew[e],       w1 = g_ew[e + 1];
        float w2 = g_ew[e + 2],   w3 = g_ew[e + 3];
        const float4* f0 = (const float4*)(feat + (size_t)s0 * DIM);
        const float4* f1 = (const float4*)(feat + (size_t)s1 * DIM);
        const float4* f2 = (const float4*)(feat + (size_t)s2 * DIM);
        const float4* f3 = (const float4*)(feat + (size_t)s3 * DIM);
        float4 v00 = f0[lane], v01 = f0[lane + 32];
        float4 v10 = f1[lane], v11 = f1[lane + 32];
        float4 v20 = f2[lane], v21 = f2[lane + 32];
        float4 v30 = f3[lane], v31 = f3[lane + 32];
        fma4(a0, w0, v00); fma4(a1, w0, v01);
        fma4(a0, w1, v10); fma4(a1, w1, v11);
        fma4(a0, w2, v20); fma4(a1, w2, v21);
        fma4(a0, w3, v30); fma4(a1, w3, v31);
    }
    for (; e + 2 <= e1; e += 2) {
        int   sA = g_esrc[e], sB = g_esrc[e + 1];
        float wA = g_ew[e],   wB = g_ew[e + 1];
        const float4* fA = (const float4*)(feat + (size_t)sA * DIM);
        const float4* fB = (const float4*)(feat + (size_t)sB * DIM);
        float4 vA0 = fA[lane], vA1 = fA[lane + 32];
        float4 vB0 = fB[lane], vB1 = fB[lane + 32];
        fma4(a0, wA, vA0); fma4(a1, wA, vA1);
        fma4(a0, wB, vB0); fma4(a1, wB, vB1);
    }
    if (e < e1) {
        int s = g_esrc[e];
        float w = g_ew[e];
        const float4* fr = (const float4*)(feat + (size_t)s * DIM);
        float4 v0 = fr[lane], v1 = fr[lane + 32];
        fma4(a0, w, v0); fma4(a1, w, v1);
    }
    // split + store bf16 hi/lo (streaming: consumed once by GEMM)
    size_t base = (size_t)node * DIM + lane * 4;
    st_cs_u2(g_a_hi + base,       make_uint2(pack_hi(a0.x, a0.y), pack_hi(a0.z, a0.w)));
    st_cs_u2(g_a_lo + base,       make_uint2(pack_lo(a0.x, a0.y), pack_lo(a0.z, a0.w)));
    st_cs_u2(g_a_hi + base + 128, make_uint2(pack_hi(a1.x, a1.y), pack_hi(a1.z, a1.w)));
    st_cs_u2(g_a_lo + base + 128, make_uint2(pack_lo(a1.x, a1.y), pack_lo(a1.z, a1.w)));
}

// ---------------- HMMA GEMM: out = relu(inv_in[i]*(A@W) + b) ----------------
// BM=128, BN=256, BK=64, 512 threads (16 warps, 2m x 8n, warp tile 64x32).
// Stage: [Ah 16K][Al 16K][Bh 32K][Bl 32K] = 96KB, x2 = 192KB. Pure cp.async.
#define TA 16384
#define OFF_B 32768
#define TB 32768
#define STAGE_B 98304

__global__ __launch_bounds__(512, 1)
void k_gemm_mma(const __nv_bfloat16* __restrict__ Bh_g,
                const __nv_bfloat16* __restrict__ Bl_g,
                const float* __restrict__ bias, float* __restrict__ out) {
    extern __shared__ char smem[];
    const uint32_t sb = smem_u32(smem);
    const int tid = threadIdx.x, lane = tid & 31, wid = tid >> 5;
    const int wm = wid >> 3, wn = wid & 7;
    const int row0 = blockIdx.x * 128;

    float acc[4][4][4];
#pragma unroll
    for (int i = 0; i < 4; i++)
#pragma unroll
        for (int j = 0; j < 4; j++)
#pragma unroll
            for (int k = 0; k < 4; k++) acc[i][j][k] = 0.f;

#define CPALL(s, c)                                                                 \
    {                                                                               \
        _Pragma("unroll")                                                           \
        for (int it = 0; it < 2; it++) {                                            \
            int id = tid + it * 512;                                                \
            int r = id >> 3, pc = id & 7;                                           \
            uint32_t dst = sb + (s) * STAGE_B + r * 128 + ((pc ^ (r & 7)) << 4);    \
            size_t aoff = (size_t)(row0 + r) * DIM + (c) * 64 + pc * 8;             \
            cp16(dst, g_a_hi + aoff);                                               \
            cp16(dst + TA, g_a_lo + aoff);                                          \
        }                                                                           \
        _Pragma("unroll")                                                           \
        for (int it = 0; it < 4; it++) {                                            \
            int id = tid + it * 512;                                                \
            int r = id >> 3, pc = id & 7;                                           \
            uint32_t dst = sb + (s) * STAGE_B + OFF_B + r * 128 + ((pc ^ (r & 7)) << 4); \
            size_t boff = (size_t)r * DIM + (c) * 64 + pc * 8;                      \
            cp16(dst, Bh_g + boff);                                                 \
            cp16(dst + TB, Bl_g + boff);                                            \
        }                                                                           \
        cp_commit();                                                                \
    }

    CPALL(0, 0);

#pragma unroll
    for (int c = 0; c < 4; c++) {
        const int s = c & 1;
        const uint32_t st = sb + s * STAGE_B;
        cp_wait0();
        __syncthreads();
        if (c < 3) CPALL(1 - s, c + 1);

#pragma unroll
        for (int k16 = 0; k16 < 4; k16++) {
            uint32_t ah[4][4], al[4][4];
#pragma unroll
            for (int fm = 0; fm < 4; fm++) {
                int row = wm * 64 + fm * 16 + (lane & 15);
                int kc = k16 * 2 + (lane >> 4);
                uint32_t a = st + row * 128 + ((kc ^ (row & 7)) << 4);
                ldm4(ah[fm], a);
                ldm4(al[fm], a + TA);
            }
            uint32_t bh[2][4], bl[2][4];
#pragma unroll
            for (int rg = 0; rg < 2; rg++) {
                int nrow = wn * 32 + rg * 16 + (lane & 7) + ((lane & 16) >> 1);
                int kc = k16 * 2 + ((lane >> 3) & 1);
                uint32_t a = st + OFF_B + nrow * 128 + ((kc ^ (nrow & 7)) << 4);
                ldm4(bh[rg], a);
                ldm4(bl[rg], a + TB);
            }
#pragma unroll
            for (int fm = 0; fm < 4; fm++)
#pragma unroll
                for (int fn = 0; fn < 4; fn++) {
                    int rg = fn >> 1, o = (fn & 1) * 2;
                    mma16816(acc[fm][fn], ah[fm], bh[rg][o], bh[rg][o + 1]);
                    mma16816(acc[fm][fn], ah[fm], bl[rg][o], bl[rg][o + 1]);
                    mma16816(acc[fm][fn], al[fm], bh[rg][o], bh[rg][o + 1]);
                }
        }
        __syncthreads();
    }

    // epilogue: dst-norm + bias + relu
#pragma unroll
    for (int fm = 0; fm < 4; fm++) {
        int mbase = row0 + wm * 64 + fm * 16 + (lane >> 2);
#pragma unroll
        for (int half = 0; half < 2; half++) {
            int row = mbase + half * 8;
            if (row >= N_NODES) continue;
            float sc = g_inv_in[row];
#pragma unroll
            for (int fn = 0; fn < 4; fn++) {
                int col = wn * 32 + fn * 8 + 2 * (lane & 3);
                float v0 = acc[fm][fn][half * 2 + 0];
                float v1 = acc[fm][fn][half * 2 + 1];
                float2 o;
                o.x = fmaxf(fmaf(v0, sc, bias[col]), 0.f);
                o.y = fmaxf(fmaf(v1, sc, bias[col + 1]), 0.f);
                *(float2*)(out + (size_t)row * DIM + col) = o;
            }
        }
    }
}

// ---------------- launch ----------------
extern "C" void kernel_launch(void* const* d_in, const int* in_sizes, int n_in,
                              void* d_out, int out_size) {
    const int*   src  = (const int*)d_in[0];
    const int*   dst  = (const int*)d_in[1];
    const float* feat = (const float*)d_in[2];
    const float* W1   = (const float*)d_in[3];
    const float* b1   = (const float*)d_in[4];
    const float* W2   = (const float*)d_in[5];
    const float* b2   = (const float*)d_in[6];
    float*       out  = (float*)d_out;

    float* h; cudaGetSymbolAddress((void**)&h, g_h);
    __nv_bfloat16 *bt1h, *bt1l, *bt2h, *bt2l;
    cudaGetSymbolAddress((void**)&bt1h, g_bt1_hi);
    cudaGetSymbolAddress((void**)&bt1l, g_bt1_lo);
    cudaGetSymbolAddress((void**)&bt2h, g_bt2_hi);
    cudaGetSymbolAddress((void**)&bt2l, g_bt2_lo);

    static int smem_set = 0;
    if (!smem_set) {
        cudaFuncSetAttribute(k_gemm_mma, cudaFuncAttributeMaxDynamicSharedMemorySize,
                             2 * STAGE_B);
        smem_set = 1;
    }

    const int T = 256;
    const int gemm_grid = (N_NODES + 127) / 128;
    const int gather_grid = (N_NODES * 32 + T - 1) / T;

    // ---- prep (5 launches) ----
    k_init_counts<<<(N_NODES + T - 1) / T, T>>>();
    k_count_prep<<<(N_EDGES + T - 1) / T, T>>>(src, dst, W1, W2);
    k_scan1<<<NBLK, SCAN_B>>>();
    k_scan3_inv<<<NBLK, SCAN_B>>>();
    k_bucket<<<(N_EDGES + T - 1) / T, T>>>(src, dst);

    // ---- layer 1 ----
    k_gather<<<gather_grid, T>>>(feat);
    k_gemm_mma<<<gemm_grid, 512, 2 * STAGE_B>>>(bt1h, bt1l, b1, h);

    // ---- layer 2 ----
    k_gather<<<gather_grid, T>>>(h);
    k_gemm_mma<<<gemm_grid, 512, 2 * STAGE_B>>>(bt2h, bt2l, b2, out);
}

// round 16
// speedup vs baseline: 1.0469x; 1.0469x over previous
#include <cuda_runtime.h>
#include <cuda_bf16.h>
#include <cstdint>

#define N_NODES 100000
#define N_EDGES 320000
#define DIM 256
#define PAD_ROWS 128

#define SCAN_B 256
#define NBLK ((N_NODES + SCAN_B - 1) / SCAN_B)

// ---------------- scratch (no allocations allowed) ----------------
__device__ int   g_deg_out[N_NODES];
__device__ int   g_deg_in[N_NODES];
__device__ float g_inv_out[N_NODES];
__device__ float g_inv_in[N_NODES];
__device__ float g_h[(size_t)N_NODES * DIM];
// gather output, pre-split bf16 (padded so full GEMM tiles read in-bounds)
__device__ __nv_bfloat16 g_a_hi[(size_t)(N_NODES + PAD_ROWS) * DIM];
__device__ __nv_bfloat16 g_a_lo[(size_t)(N_NODES + PAD_ROWS) * DIM];
// CSR (by dst)
__device__ int g_off[N_NODES + 1];
__device__ int g_cur[N_NODES];
__device__ int g_part[NBLK];
__device__ int g_esrc[N_EDGES];
// W transposed to [N,K], bf16 hi/lo
__device__ __nv_bfloat16 g_bt1_hi[DIM * DIM];
__device__ __nv_bfloat16 g_bt1_lo[DIM * DIM];
__device__ __nv_bfloat16 g_bt2_hi[DIM * DIM];
__device__ __nv_bfloat16 g_bt2_lo[DIM * DIM];

// ---------------- helpers ----------------
__device__ __forceinline__ uint32_t smem_u32(const void* p) {
    uint32_t a;
    asm("{ .reg .u64 t; cvta.to.shared.u64 t, %1; cvt.u32.u64 %0, t; }" : "=r"(a) : "l"(p));
    return a;
}
__device__ __forceinline__ void cp16(uint32_t dst, const void* src) {
    asm volatile("cp.async.cg.shared.global [%0], [%1], 16;"
                 :: "r"(dst), "l"(src) : "memory");
}
__device__ __forceinline__ void cp_commit() {
    asm volatile("cp.async.commit_group;" ::: "memory");
}
__device__ __forceinline__ void cp_wait0() {
    asm volatile("cp.async.wait_group 0;" ::: "memory");
}
__device__ __forceinline__ void ldm4(uint32_t* r, uint32_t addr) {
    asm volatile("ldmatrix.sync.aligned.m8n8.x4.shared.b16 {%0,%1,%2,%3}, [%4];"
                 : "=r"(r[0]), "=r"(r[1]), "=r"(r[2]), "=r"(r[3]) : "r"(addr));
}
__device__ __forceinline__ void mma16816(float* c, const uint32_t* a, uint32_t b0, uint32_t b1) {
    asm volatile("mma.sync.aligned.m16n8k16.row.col.f32.bf16.bf16.f32 "
                 "{%0,%1,%2,%3}, {%4,%5,%6,%7}, {%8,%9}, {%0,%1,%2,%3};"
                 : "+f"(c[0]), "+f"(c[1]), "+f"(c[2]), "+f"(c[3])
                 : "r"(a[0]), "r"(a[1]), "r"(a[2]), "r"(a[3]), "r"(b0), "r"(b1));
}
__device__ __forceinline__ uint32_t pack_hi(float x, float y) {
    return (uint32_t)__bfloat16_as_ushort(__float2bfloat16(x)) |
           ((uint32_t)__bfloat16_as_ushort(__float2bfloat16(y)) << 16);
}
__device__ __forceinline__ uint32_t pack_lo(float x, float y) {
    float rx = x - __bfloat162float(__float2bfloat16(x));
    float ry = y - __bfloat162float(__float2bfloat16(y));
    return (uint32_t)__bfloat16_as_ushort(__float2bfloat16(rx)) |
           ((uint32_t)__bfloat16_as_ushort(__float2bfloat16(ry)) << 16);
}
__device__ __forceinline__ void st_cs_u2(void* p, uint2 v) {
    asm volatile("st.global.cs.v2.u32 [%0], {%1, %2};"
                 :: "l"(p), "r"(v.x), "r"(v.y) : "memory");
}
__device__ __forceinline__ void fma4(float4& a, float w, const float4& v) {
    a.x = fmaf(w, v.x, a.x); a.y = fmaf(w, v.y, a.y);
    a.z = fmaf(w, v.z, a.z); a.w = fmaf(w, v.w, a.w);
}

// ---------------- graph prep (compact: 5 launches) ----------------
__global__ void k_init_counts() {
    int i = blockIdx.x * blockDim.x + threadIdx.x;
    if (i < N_NODES) { g_deg_out[i] = 0; g_deg_in[i] = 0; }
}
// degree count + weight split fused (independent work, one launch)
__global__ void k_count_prep(const int* __restrict__ src, const int* __restrict__ dst,
                             const float* __restrict__ W1, const float* __restrict__ W2) {
    int i = blockIdx.x * blockDim.x + threadIdx.x;
    if (i < N_EDGES) {
        atomicAdd(&g_deg_out[src[i]], 1);
        atomicAdd(&g_deg_in[dst[i]], 1);
    }
    if (i < 2 * DIM * DIM) {
        int layer = i >= DIM * DIM;
        int j = i - layer * DIM * DIM;
        int n = j >> 8, k = j & 255;
        float v = layer ? W2[k * DIM + n] : W1[k * DIM + n];
        __nv_bfloat16 h = __float2bfloat16(v);
        float l = v - __bfloat162float(h);
        if (layer) { g_bt2_hi[j] = h; g_bt2_lo[j] = __float2bfloat16(l); }
        else       { g_bt1_hi[j] = h; g_bt1_lo[j] = __float2bfloat16(l); }
    }
}
__global__ void k_scan1() {
    __shared__ int sh[SCAN_B];
    int i = blockIdx.x * SCAN_B + threadIdx.x;
    int v = (i < N_NODES) ? g_deg_in[i] : 0;
    sh[threadIdx.x] = v;
    __syncthreads();
#pragma unroll
    for (int o = 1; o < SCAN_B; o <<= 1) {
        int t = (threadIdx.x >= o) ? sh[threadIdx.x - o] : 0;
        __syncthreads();
        sh[threadIdx.x] += t;
        __syncthreads();
    }
    if (i < N_NODES) g_off[i] = sh[threadIdx.x] - v;
    if (threadIdx.x == SCAN_B - 1) g_part[blockIdx.x] = sh[SCAN_B - 1];
}
// per-block prefix of partials computed redundantly (replaces scan2)
__global__ void k_scan3_inv() {
    __shared__ int sred[SCAN_B];
    int t = threadIdx.x, b = blockIdx.x;
    int acc = 0;
    for (int j = t; j < b; j += SCAN_B) acc += g_part[j];
    sred[t] = acc;
    __syncthreads();
#pragma unroll
    for (int o = SCAN_B / 2; o > 0; o >>= 1) {
        if (t < o) sred[t] += sred[t + o];
        __syncthreads();
    }
    int prefix = sred[0];
    int i = b * SCAN_B + t;
    if (i < N_NODES) {
        int o = g_off[i] + prefix;
        g_off[i] = o;
        g_cur[i] = o;
        g_inv_out[i] = rsqrtf(fmaxf((float)g_deg_out[i], 1.0f));
        g_inv_in[i]  = rsqrtf(fmaxf((float)g_deg_in[i], 1.0f));
    }
    if (i == 0) g_off[N_NODES] = N_EDGES;
}
__global__ void k_bucket(const int* __restrict__ src, const int* __restrict__ dst) {
    int e = blockIdx.x * blockDim.x + threadIdx.x;
    if (e < N_EDGES) {
        int p = atomicAdd(&g_cur[dst[e]], 1);
        g_esrc[p] = src[e];
    }
}

// ---------------- CSR gather + bf16 split (proven R7 form) ----------------
// One warp per node; lane owns float4 cols {4*lane, 4*lane+128}. 4-edge MLP batches.
__global__ __launch_bounds__(256)
void k_gather(const float* __restrict__ feat) {
    int node = (blockIdx.x * blockDim.x + threadIdx.x) >> 5;
    int lane = threadIdx.x & 31;
    if (node >= N_NODES) return;
    int e0 = g_off[node], e1 = g_off[node + 1];

    float4 a0 = make_float4(0.f, 0.f, 0.f, 0.f);
    float4 a1 = a0;

    int e = e0;
    for (; e + 4 <= e1; e += 4) {
        int   s0 = g_esrc[e],     s1 = g_esrc[e + 1];
        int   s2 = g_esrc[e + 2], s3 = g_esrc[e + 3];
        float w0 = g_inv_out[s0], w1 = g_inv_out[s1];
        float w2 = g_inv_out[s2], w3 = g_inv_out[s3];
        const float4* f0 = (const float4*)(feat + (size_t)s0 * DIM);
        const float4* f1 = (const float4*)(feat + (size_t)s1 * DIM);
        const float4* f2 = (const float4*)(feat + (size_t)s2 * DIM);
        const float4* f3 = (const float4*)(feat + (size_t)s3 * DIM);
        float4 v00 = f0[lane], v01 = f0[lane + 32];
        float4 v10 = f1[lane], v11 = f1[lane + 32];
        float4 v20 = f2[lane], v21 = f2[lane + 32];
        float4 v30 = f3[lane], v31 = f3[lane + 32];
        fma4(a0, w0, v00); fma4(a1, w0, v01);
        fma4(a0, w1, v10); fma4(a1, w1, v11);
        fma4(a0, w2, v20); fma4(a1, w2, v21);
        fma4(a0, w3, v30); fma4(a1, w3, v31);
    }
    for (; e + 2 <= e1; e += 2) {
        int   sA = g_esrc[e], sB = g_esrc[e + 1];
        float wA = g_inv_out[sA], wB = g_inv_out[sB];
        const float4* fA = (const float4*)(feat + (size_t)sA * DIM);
        const float4* fB = (const float4*)(feat + (size_t)sB * DIM);
        float4 vA0 = fA[lane], vA1 = fA[lane + 32];
        float4 vB0 = fB[lane], vB1 = fB[lane + 32];
        fma4(a0, wA, vA0); fma4(a1, wA, vA1);
        fma4(a0, wB, vB0); fma4(a1, wB, vB1);
    }
    if (e < e1) {
        int s = g_esrc[e];
        float w = g_inv_out[s];
        const float4* fr = (const float4*)(feat + (size_t)s * DIM);
        float4 v0 = fr[lane], v1 = fr[lane + 32];
        fma4(a0, w, v0); fma4(a1, w, v1);
    }
    // split + store bf16 hi/lo (streaming: consumed once by GEMM)
    size_t base = (size_t)node * DIM + lane * 4;
    st_cs_u2(g_a_hi + base,       make_uint2(pack_hi(a0.x, a0.y), pack_hi(a0.z, a0.w)));
    st_cs_u2(g_a_lo + base,       make_uint2(pack_lo(a0.x, a0.y), pack_lo(a0.z, a0.w)));
    st_cs_u2(g_a_hi + base + 128, make_uint2(pack_hi(a1.x, a1.y), pack_hi(a1.z, a1.w)));
    st_cs_u2(g_a_lo + base + 128, make_uint2(pack_lo(a1.x, a1.y), pack_lo(a1.z, a1.w)));
}

// ---------------- HMMA GEMM: out = relu(inv_in[i]*(A@W) + b) ----------------
// BM=128, BN=256, BK=64, 512 threads (16 warps, 2m x 8n, warp tile 64x32).
// Stage: [Ah 16K][Al 16K][Bh 32K][Bl 32K] = 96KB, x2 = 192KB. Pure cp.async.
#define TA 16384
#define OFF_B 32768
#define TB 32768
#define STAGE_B 98304

__global__ __launch_bounds__(512, 1)
void k_gemm_mma(const __nv_bfloat16* __restrict__ Bh_g,
                const __nv_bfloat16* __restrict__ Bl_g,
                const float* __restrict__ bias, float* __restrict__ out) {
    extern __shared__ char smem[];
    const uint32_t sb = smem_u32(smem);
    const int tid = threadIdx.x, lane = tid & 31, wid = tid >> 5;
    const int wm = wid >> 3, wn = wid & 7;
    const int row0 = blockIdx.x * 128;

    float acc[4][4][4];
#pragma unroll
    for (int i = 0; i < 4; i++)
#pragma unroll
        for (int j = 0; j < 4; j++)
#pragma unroll
            for (int k = 0; k < 4; k++) acc[i][j][k] = 0.f;

#define CPALL(s, c)                                                                 \
    {                                                                               \
        _Pragma("unroll")                                                           \
        for (int it = 0; it < 2; it++) {                                            \
            int id = tid + it * 512;                                                \
            int r = id >> 3, pc = id & 7;                                           \
            uint32_t dst = sb + (s) * STAGE_B + r * 128 + ((pc ^ (r & 7)) << 4);    \
            size_t aoff = (size_t)(row0 + r) * DIM + (c) * 64 + pc * 8;             \
            cp16(dst, g_a_hi + aoff);                                               \
            cp16(dst + TA, g_a_lo + aoff);                                          \
        }                                                                           \
        _Pragma("unroll")                                                           \
        for (int it = 0; it < 4; it++) {                                            \
            int id = tid + it * 512;                                                \
            int r = id >> 3, pc = id & 7;                                           \
            uint32_t dst = sb + (s) * STAGE_B + OFF_B + r * 128 + ((pc ^ (r & 7)) << 4); \
            size_t boff = (size_t)r * DIM + (c) * 64 + pc * 8;                      \
            cp16(dst, Bh_g + boff);                                                 \
            cp16(dst + TB, Bl_g + boff);                                            \
        }                                                                           \
        cp_commit();                                                                \
    }

    CPALL(0, 0);

#pragma unroll
    for (int c = 0; c < 4; c++) {
        const int s = c & 1;
        const uint32_t st = sb + s * STAGE_B;
        cp_wait0();
        __syncthreads();
        if (c < 3) CPALL(1 - s, c + 1);

#pragma unroll
        for (int k16 = 0; k16 < 4; k16++) {
            uint32_t ah[4][4], al[4][4];
#pragma unroll
            for (int fm = 0; fm < 4; fm++) {
                int row = wm * 64 + fm * 16 + (lane & 15);
                int kc = k16 * 2 + (lane >> 4);
                uint32_t a = st + row * 128 + ((kc ^ (row & 7)) << 4);
                ldm4(ah[fm], a);
                ldm4(al[fm], a + TA);
            }
            uint32_t bh[2][4], bl[2][4];
#pragma unroll
            for (int rg = 0; rg < 2; rg++) {
                int nrow = wn * 32 + rg * 16 + (lane & 7) + ((lane & 16) >> 1);
                int kc = k16 * 2 + ((lane >> 3) & 1);
                uint32_t a = st + OFF_B + nrow * 128 + ((kc ^ (nrow & 7)) << 4);
                ldm4(bh[rg], a);
                ldm4(bl[rg], a + TB);
            }
#pragma unroll
            for (int fm = 0; fm < 4; fm++)
#pragma unroll
                for (int fn = 0; fn < 4; fn++) {
                    int rg = fn >> 1, o = (fn & 1) * 2;
                    mma16816(acc[fm][fn], ah[fm], bh[rg][o], bh[rg][o + 1]);
                    mma16816(acc[fm][fn], ah[fm], bl[rg][o], bl[rg][o + 1]);
                    mma16816(acc[fm][fn], al[fm], bh[rg][o], bh[rg][o + 1]);
                }
        }
        __syncthreads();
    }

    // epilogue: dst-norm + bias + relu
#pragma unroll
    for (int fm = 0; fm < 4; fm++) {
        int mbase = row0 + wm * 64 + fm * 16 + (lane >> 2);
#pragma unroll
        for (int half = 0; half < 2; half++) {
            int row = mbase + half * 8;
            if (row >= N_NODES) continue;
            float sc = g_inv_in[row];
#pragma unroll
            for (int fn = 0; fn < 4; fn++) {
                int col = wn * 32 + fn * 8 + 2 * (lane & 3);
                float v0 = acc[fm][fn][half * 2 + 0];
                float v1 = acc[fm][fn][half * 2 + 1];
                float2 o;
                o.x = fmaxf(fmaf(v0, sc, bias[col]), 0.f);
                o.y = fmaxf(fmaf(v1, sc, bias[col + 1]), 0.f);
                *(float2*)(out + (size_t)row * DIM + col) = o;
            }
        }
    }
}

// ---------------- launch ----------------
extern "C" void kernel_launch(void* const* d_in, const int* in_sizes, int n_in,
                              void* d_out, int out_size) {
    const int*   src  = (const int*)d_in[0];
    const int*   dst  = (const int*)d_in[1];
    const float* feat = (const float*)d_in[2];
    const float* W1   = (const float*)d_in[3];
    const float* b1   = (const float*)d_in[4];
    const float* W2   = (const float*)d_in[5];
    const float* b2   = (const float*)d_in[6];
    float*       out  = (float*)d_out;

    float* h; cudaGetSymbolAddress((void**)&h, g_h);
    __nv_bfloat16 *bt1h, *bt1l, *bt2h, *bt2l;
    cudaGetSymbolAddress((void**)&bt1h, g_bt1_hi);
    cudaGetSymbolAddress((void**)&bt1l, g_bt1_lo);
    cudaGetSymbolAddress((void**)&bt2h, g_bt2_hi);
    cudaGetSymbolAddress((void**)&bt2l, g_bt2_lo);

    static int smem_set = 0;
    if (!smem_set) {
        cudaFuncSetAttribute(k_gemm_mma, cudaFuncAttributeMaxDynamicSharedMemorySize,
                             2 * STAGE_B);
        smem_set = 1;
    }

    const int T = 256;
    const int gemm_grid = (N_NODES + 127) / 128;
    const int gather_grid = (N_NODES * 32 + T - 1) / T;

    // ---- prep (5 launches) ----
    k_init_counts<<<(N_NODES + T - 1) / T, T>>>();
    k_count_prep<<<(N_EDGES + T - 1) / T, T>>>(src, dst, W1, W2);
    k_scan1<<<NBLK, SCAN_B>>>();
    k_scan3_inv<<<NBLK, SCAN_B>>>();
    k_bucket<<<(N_EDGES + T - 1) / T, T>>>(src, dst);

    // ---- layer 1 ----
    k_gather<<<gather_grid, T>>>(feat);
    k_gemm_mma<<<gemm_grid, 512, 2 * STAGE_B>>>(bt1h, bt1l, b1, h);

    // ---- layer 2 ----
    k_gather<<<gather_grid, T>>>(h);
    k_gemm_mma<<<gemm_grid, 512, 2 * STAGE_B>>>(bt2h, bt2l, b2, out);
}